// round 4
// baseline (speedup 1.0000x reference)
#include <cuda_runtime.h>
#include <math.h>

// Problem constants
#define BATCH 4096
#define DIM   64

// Tiling: 64-thread CTA (2 warps); thread tid owns output component i = tid
// for R=4 batch rows. 1024 CTAs -> 2048 warps (13.8/SM).
#define R        4
#define THREADS  64
#define NBLOCKS  (BATCH / R)          // 1024

#define MAX_IT 100
#define DTOL   6e-4f

typedef unsigned long long u64;

__device__ __forceinline__ u64 pk(float lo, float hi) {
    u64 r; asm("mov.b64 %0, {%1, %2};" : "=l"(r) : "f"(lo), "f"(hi)); return r;
}
__device__ __forceinline__ void upk(float& lo, float& hi, u64 v) {
    asm("mov.b64 {%0, %1}, %2;" : "=f"(lo), "=f"(hi) : "l"(v));
}
// Packed dual-FMA on the FMA pipe: d.lo += a.lo*b.lo ; d.hi += a.hi*b.hi
__device__ __forceinline__ void fma2(u64& d, u64 a, u64 b) {
    asm("fma.rn.f32x2 %0, %1, %2, %0;" : "+l"(d) : "l"(a), "l"(b));
}

// Accurate tanh (~1e-6 abs err): MUFU.EX2 + MUFU.RCP, fast-math-proof.
__device__ __forceinline__ float my_tanh(float a) {
    float aa = fabsf(a);
    float e  = __expf(-2.0f * aa);                 // in (0, 1]
    float t  = __fdividef(1.0f - e, 1.0f + e);     // denom in [1,2]: safe
    return copysignf(t, a);
}

__global__ void __launch_bounds__(THREADS)
tanh_fixed_point_kernel(const float* __restrict__ x,
                        const float* __restrict__ W,
                        float* __restrict__ out)
{
    // Ping-pong z buffers: zsh[p][r][j]
    __shared__ __align__(16) float zsh[2][R][DIM];

    const int tid = threadIdx.x;

    // W row i=tid -> registers as packed consecutive-j pairs:
    //   w[jc] = (W[tid][2jc], W[tid][2jc+1]),  jc = 0..31   (64 regs)
    u64 w[32];
    {
        const ulonglong2* Wrow = reinterpret_cast<const ulonglong2*>(W + tid * DIM);
        #pragma unroll
        for (int q = 0; q < 16; q++) {
            ulonglong2 v = Wrow[q];       // LDG.128, one-time, L2-hot
            w[2 * q]     = v.x;
            w[2 * q + 1] = v.y;
        }
    }

    const int row0 = blockIdx.x * R;

    float xr[R], z[R];
    #pragma unroll
    for (int r = 0; r < R; r++) {
        xr[r] = x[(row0 + r) * DIM + tid];
        z[r]  = my_tanh(xr[r]);
        zsh[0][r][tid] = z[r];
    }
    __syncthreads();

    int p = 0;
    for (int it = 0; it < MAX_IT; it++) {
        // acc[r][0]: even-jq chain (x folded in), acc[r][1]: odd-jq chain.
        // Within each jq, the two packed products go to different chains ->
        // dependency depth 16 per chain (8 independent chains total).
        u64 acc0[R], acc1[R];
        #pragma unroll
        for (int r = 0; r < R; r++) {
            acc0[r] = pk(xr[r], 0.0f);
            acc1[r] = pk(0.0f, 0.0f);
        }

        #pragma unroll
        for (int jq = 0; jq < 16; jq++) {
            #pragma unroll
            for (int r = 0; r < R; r++) {
                // (z_{2jq},z_{2jq+1}),(z_{2jq+2},z_{2jq+3}) broadcast
                ulonglong2 zp = reinterpret_cast<const ulonglong2*>(zsh[p][r])[jq];
                fma2(acc0[r], w[2 * jq],     zp.x);
                fma2(acc1[r], w[2 * jq + 1], zp.y);
            }
        }

        bool conv = true;
        #pragma unroll
        for (int r = 0; r < R; r++) {
            float a0, a1, b0, b1;
            upk(a0, a1, acc0[r]);
            upk(b0, b1, acc1[r]);
            float n = my_tanh((a0 + b0) + (a1 + b1));
            conv = conv && (fabsf(n - z[r]) < DTOL);
            z[r] = n;
            zsh[p ^ 1][r][tid] = n;           // store into the other buffer
        }

        p ^= 1;
        // One barrier per iteration: orders stores(k) before reads(k+1),
        // reads(k) before stores(k+2), and reduces convergence block-wide.
        int allc = __syncthreads_and(conv ? 1 : 0);
        if (allc) break;
    }

    #pragma unroll
    for (int r = 0; r < R; r++)
        out[(row0 + r) * DIM + tid] = z[r];
}

extern "C" void kernel_launch(void* const* d_in, const int* in_sizes, int n_in,
                              void* d_out, int out_size)
{
    const float* x = (const float*)d_in[0];   // [4096, 64]
    const float* W = (const float*)d_in[1];   // [64, 64]
    float* out = (float*)d_out;               // [4096, 64]
    (void)in_sizes; (void)n_in; (void)out_size;

    tanh_fixed_point_kernel<<<NBLOCKS, THREADS>>>(x, W, out);
}